// round 1
// baseline (speedup 1.0000x reference)
#include <cuda_runtime.h>

#define NN 50000
#define NE 1600000
#define FIN 128
#define FOUT 64
#define NH 4
#define NCOLS 640   // [u0 u1 u2 u3 | v0 v1 v2 v3 | m_nb | m_self] each 64

// ---- scratch (static __device__; no runtime allocation) ----
__device__ float g_nodeData[(size_t)NN * NCOLS];   // 128 MB
__device__ float g_Wc[FIN * NCOLS];
__device__ float g_biasC[NCOLS];
__device__ float g_selfDen[(size_t)NN * FOUT];
__device__ float g_selfNum[(size_t)NN * FOUT];
__device__ int   g_cnt[NN];
__device__ int   g_off[NN + 1];
__device__ int   g_cursor[NN];
__device__ int   g_srcSorted[NE];

// ============================================================
// 1) Fold weights:  Wc[128][640], biasC[640]
//    cols [0,256):    WU_i = Wt_i @ Wa_i[0:64]   bias = bt_i@Wa_top + ba_i
//    cols [256,512):  WV_i = Wt_i @ Wa_i[64:128] bias = bt_i@Wa_bot
//    cols [512,576):  Wn (bias bn);  cols [576,640): Wv (bias bv)
// ============================================================
__global__ void prep_kernel(const float* __restrict__ Wt, const float* __restrict__ bt,
                            const float* __restrict__ Wa, const float* __restrict__ ba,
                            const float* __restrict__ Wn, const float* __restrict__ bn,
                            const float* __restrict__ Wv, const float* __restrict__ bv) {
    int col = blockIdx.x;       // 0..639
    int r   = threadIdx.x;      // 0..127
    float w;
    if (col < 512) {
        int uv = col >> 8;           // 0 = U, 1 = V
        int i  = (col >> 6) & 3;     // head
        int cc = col & 63;
        const float* wt = Wt + ((size_t)(i * FIN) + r) * FOUT;              // Wt[i][r][k]
        const float* wa = Wa + ((size_t)i * 2 * FOUT + uv * FOUT) * FOUT + cc; // Wa[i][uv*64+k][cc]
        float s = 0.f;
        #pragma unroll 8
        for (int k = 0; k < FOUT; k++) s = fmaf(wt[k], wa[(size_t)k * FOUT], s);
        w = s;
        if (r == 0) {
            const float* bti = bt + i * FOUT;
            float sb = 0.f;
            for (int k = 0; k < FOUT; k++) sb = fmaf(bti[k], wa[(size_t)k * FOUT], sb);
            if (uv == 0) sb += ba[i * FOUT + cc];
            g_biasC[col] = sb;
        }
    } else if (col < 576) {
        int cc = col - 512;
        w = Wn[(size_t)r * FOUT + cc];
        if (r == 0) g_biasC[col] = bn[cc];
    } else {
        int cc = col - 576;
        w = Wv[(size_t)r * FOUT + cc];
        if (r == 0) g_biasC[col] = bv[cc];
    }
    g_Wc[(size_t)r * NCOLS + col] = w;
}

// ============================================================
// 2) Fused node GEMM: nodeData[N][640] = X[N][128] @ Wc + biasC
//    Tiles: BM=128, BN=64, BK=16; 256 threads, 8x4 per thread; double-buffered smem
// ============================================================
__global__ __launch_bounds__(256) void gemm_kernel(const float* __restrict__ X) {
    __shared__ float As[2][16][128];
    __shared__ float Bs[2][16][64];
    const int tid = threadIdx.x;
    const int bm = blockIdx.x * 128;
    const int bn = blockIdx.y * 64;

    const int lm  = tid >> 1;            // 0..127 row in A tile
    const int lk  = (tid & 1) << 3;      // 0 or 8
    const int bkr = tid >> 4;            // 0..15 row of B chunk
    const int bnc = (tid & 15) << 2;     // col*4
    const int rg  = tid >> 4;            // row group (x8)
    const int cg  = tid & 15;            // col group (x4)

    const int  row   = bm + lm;
    const bool rowOK = row < NN;
    const float* xrow = X + (size_t)row * FIN;

    float acc[8][4];
    #pragma unroll
    for (int i = 0; i < 8; i++)
        #pragma unroll
        for (int j = 0; j < 4; j++) acc[i][j] = 0.f;

    // prologue: load chunk 0
    {
        float4 a0 = make_float4(0, 0, 0, 0), a1 = a0;
        if (rowOK) { a0 = *(const float4*)(xrow + lk); a1 = *(const float4*)(xrow + lk + 4); }
        As[0][lk + 0][lm] = a0.x; As[0][lk + 1][lm] = a0.y;
        As[0][lk + 2][lm] = a0.z; As[0][lk + 3][lm] = a0.w;
        As[0][lk + 4][lm] = a1.x; As[0][lk + 5][lm] = a1.y;
        As[0][lk + 6][lm] = a1.z; As[0][lk + 7][lm] = a1.w;
        *(float4*)&Bs[0][bkr][bnc] = *(const float4*)(g_Wc + (size_t)bkr * NCOLS + bn + bnc);
    }
    __syncthreads();

    #pragma unroll
    for (int kc = 0; kc < 8; kc++) {
        const int cur = kc & 1;
        if (kc < 7) {
            const int nxt = cur ^ 1;
            const int k0 = (kc + 1) * 16;
            float4 a0 = make_float4(0, 0, 0, 0), a1 = a0;
            if (rowOK) { a0 = *(const float4*)(xrow + k0 + lk); a1 = *(const float4*)(xrow + k0 + lk + 4); }
            As[nxt][lk + 0][lm] = a0.x; As[nxt][lk + 1][lm] = a0.y;
            As[nxt][lk + 2][lm] = a0.z; As[nxt][lk + 3][lm] = a0.w;
            As[nxt][lk + 4][lm] = a1.x; As[nxt][lk + 5][lm] = a1.y;
            As[nxt][lk + 6][lm] = a1.z; As[nxt][lk + 7][lm] = a1.w;
            *(float4*)&Bs[nxt][bkr][bnc] = *(const float4*)(g_Wc + (size_t)(k0 + bkr) * NCOLS + bn + bnc);
        }
        #pragma unroll
        for (int k = 0; k < 16; k++) {
            float4 a0 = *(const float4*)&As[cur][k][rg << 3];
            float4 a1 = *(const float4*)&As[cur][k][(rg << 3) + 4];
            float4 b  = *(const float4*)&Bs[cur][k][cg << 2];
            float av[8] = {a0.x, a0.y, a0.z, a0.w, a1.x, a1.y, a1.z, a1.w};
            float bb[4] = {b.x, b.y, b.z, b.w};
            #pragma unroll
            for (int i = 0; i < 8; i++)
                #pragma unroll
                for (int j = 0; j < 4; j++)
                    acc[i][j] = fmaf(av[i], bb[j], acc[i][j]);
        }
        __syncthreads();
    }

    float4 bias = *(const float4*)(g_biasC + bn + (cg << 2));
    #pragma unroll
    for (int i = 0; i < 8; i++) {
        int r = bm + (rg << 3) + i;
        if (r < NN) {
            float4 o;
            o.x = acc[i][0] + bias.x; o.y = acc[i][1] + bias.y;
            o.z = acc[i][2] + bias.z; o.w = acc[i][3] + bias.w;
            *(float4*)(g_nodeData + (size_t)r * NCOLS + bn + (cg << 2)) = o;
        }
    }
}

// ============================================================
// 3) Self term: e_self, init num/den
// ============================================================
__global__ void self_kernel() {
    int idx = blockIdx.x * blockDim.x + threadIdx.x;
    if (idx >= NN * FOUT) return;
    int n = idx >> 6, c = idx & 63;
    const float* p = g_nodeData + (size_t)n * NCOLS;
    float s = 0.f;
    #pragma unroll
    for (int i = 0; i < 4; i++)
        s += fmaxf(p[i * 64 + c] + p[256 + i * 64 + c], 0.f);
    float e = __expf(0.25f * s);
    g_selfDen[idx] = e;
    g_selfNum[idx] = e * p[576 + c];
}

// ============================================================
// 4) CSR-by-dst build: zero -> histogram -> scan -> scatter
// ============================================================
__global__ void zero_kernel() {
    int i = blockIdx.x * blockDim.x + threadIdx.x;
    if (i < NN) g_cnt[i] = 0;
}

__global__ void hist_kernel(const int* __restrict__ dst) {
    int i = blockIdx.x * blockDim.x + threadIdx.x;
    if (i < NE) atomicAdd(&g_cnt[dst[i]], 1);
}

__global__ void scan_kernel() {
    __shared__ int sm[1024];
    const int t = threadIdx.x;
    int carry = 0;
    for (int base = 0; base < NN; base += 1024) {
        int v = (base + t < NN) ? g_cnt[base + t] : 0;
        sm[t] = v;
        __syncthreads();
        for (int ofs = 1; ofs < 1024; ofs <<= 1) {
            int add = (t >= ofs) ? sm[t - ofs] : 0;
            __syncthreads();
            sm[t] += add;
            __syncthreads();
        }
        int incl = sm[t];
        if (base + t < NN) {
            int ex = carry + incl - v;
            g_off[base + t] = ex;
            g_cursor[base + t] = ex;
        }
        int tot = carry + sm[1023];
        __syncthreads();
        carry = tot;
    }
    if (t == 0) g_off[NN] = carry;
}

__global__ void scatter_kernel(const int* __restrict__ src, const int* __restrict__ dst) {
    int i = blockIdx.x * blockDim.x + threadIdx.x;
    if (i < NE) {
        int d = dst[i];
        int pos = atomicAdd(&g_cursor[d], 1);
        g_srcSorted[pos] = src[i];
    }
}

// ============================================================
// 5) Edge aggregation: one block per dst node; u[dst] in registers,
//    gather v[src]+m_nb[src] coalesced; no atomics.
// ============================================================
__global__ __launch_bounds__(64) void edge_kernel(float* __restrict__ out) {
    const int n = blockIdx.x;
    const int c = threadIdx.x;   // channel 0..63
    const float* un = g_nodeData + (size_t)n * NCOLS;
    const float u0 = un[c], u1 = un[64 + c], u2 = un[128 + c], u3 = un[192 + c];
    float den = g_selfDen[(size_t)n * 64 + c];
    float num = g_selfNum[(size_t)n * 64 + c];
    const int b0 = g_off[n], b1 = g_off[n + 1];
    __shared__ int sS[128];
    for (int base = b0; base < b1; base += 128) {
        int cnt = min(128, b1 - base);
        if (base + c < b1)      sS[c]      = g_srcSorted[base + c];
        if (base + 64 + c < b1) sS[64 + c] = g_srcSorted[base + 64 + c];
        __syncthreads();
        #pragma unroll 2
        for (int j = 0; j < cnt; j++) {
            const float* p = g_nodeData + (size_t)sS[j] * NCOLS;
            float v0 = p[256 + c], v1 = p[320 + c], v2 = p[384 + c], v3 = p[448 + c];
            float m  = p[512 + c];
            float s = fmaxf(u0 + v0, 0.f) + fmaxf(u1 + v1, 0.f)
                    + fmaxf(u2 + v2, 0.f) + fmaxf(u3 + v3, 0.f);
            float w = __expf(0.25f * s);
            den += w;
            num = fmaf(w, m, num);
        }
        __syncthreads();
    }
    out[(size_t)n * 64 + c] = fmaxf(__fdividef(num, den), 0.f);
}

// ============================================================
extern "C" void kernel_launch(void* const* d_in, const int* in_sizes, int n_in,
                              void* d_out, int out_size) {
    const float* x  = (const float*)d_in[0];
    const int*   src = (const int*)d_in[1];
    const int*   dst = (const int*)d_in[2];
    const float* Wv = (const float*)d_in[3];
    const float* bv = (const float*)d_in[4];
    const float* Wn = (const float*)d_in[5];
    const float* bn = (const float*)d_in[6];
    const float* Wt = (const float*)d_in[7];
    const float* bt = (const float*)d_in[8];
    const float* Wa = (const float*)d_in[9];
    const float* ba = (const float*)d_in[10];
    float* out = (float*)d_out;

    prep_kernel<<<NCOLS, 128>>>(Wt, bt, Wa, ba, Wn, bn, Wv, bv);

    dim3 ggrid((NN + 127) / 128, NCOLS / 64);
    gemm_kernel<<<ggrid, 256>>>(x);

    self_kernel<<<(NN * FOUT + 255) / 256, 256>>>();

    zero_kernel<<<(NN + 255) / 256, 256>>>();
    hist_kernel<<<(NE + 255) / 256, 256>>>(dst);
    scan_kernel<<<1, 1024>>>();
    scatter_kernel<<<(NE + 255) / 256, 256>>>(src, dst);

    edge_kernel<<<NN, 64>>>(out);
}

// round 3
// speedup vs baseline: 1.5862x; 1.5862x over previous
#include <cuda_runtime.h>
#include <cstdint>

#define NN 50000
#define NE 1600000
#define FIN 128
#define FOUT 64
#define NCOLS 640
#define SIDE 320   // per-side row: 4*64 + 64

// ---- scratch ----
__device__ float g_dstSide[(size_t)NN * SIDE];  // u0..u3 | m_self
__device__ float g_srcSide[(size_t)NN * SIDE];  // v0..v3 | m_nb
__device__ float g_Wc[FIN * NCOLS];
__device__ float g_biasC[NCOLS];
__device__ int   g_cnt[NN];
__device__ int   g_off[NN + 1];
__device__ int   g_cursor[NN];
__device__ int   g_srcSorted[NE];
__device__ int   g_blkSum[64];
__device__ int   g_blkOff[64];

// ============================================================
// 1) Fold weights into Wc[128][640] + biasC[640]
// cols [0,256): U_i = Wt_i@Wa_i[0:64]   [256,512): V_i = Wt_i@Wa_i[64:128]
// [512,576): Wn   [576,640): Wv
// ============================================================
__global__ void prep_kernel(const float* __restrict__ Wt, const float* __restrict__ bt,
                            const float* __restrict__ Wa, const float* __restrict__ ba,
                            const float* __restrict__ Wn, const float* __restrict__ bn,
                            const float* __restrict__ Wv, const float* __restrict__ bv) {
    int col = blockIdx.x;
    int r   = threadIdx.x;
    float w;
    if (col < 512) {
        int uv = col >> 8;
        int i  = (col >> 6) & 3;
        int cc = col & 63;
        const float* wt = Wt + ((size_t)(i * FIN) + r) * FOUT;
        const float* wa = Wa + ((size_t)i * 2 * FOUT + uv * FOUT) * FOUT + cc;
        float s = 0.f;
        #pragma unroll 8
        for (int k = 0; k < FOUT; k++) s = fmaf(wt[k], wa[(size_t)k * FOUT], s);
        w = s;
        if (r == 0) {
            const float* bti = bt + i * FOUT;
            float sb = 0.f;
            for (int k = 0; k < FOUT; k++) sb = fmaf(bti[k], wa[(size_t)k * FOUT], sb);
            if (uv == 0) sb += ba[i * FOUT + cc];
            g_biasC[col] = sb;
        }
    } else if (col < 576) {
        int cc = col - 512;
        w = Wn[(size_t)r * FOUT + cc];
        if (r == 0) g_biasC[col] = bn[cc];
    } else {
        int cc = col - 576;
        w = Wv[(size_t)r * FOUT + cc];
        if (r == 0) g_biasC[col] = bv[cc];
    }
    g_Wc[(size_t)r * NCOLS + col] = w;
}

// ============================================================
// 2) tf32 tensor-core GEMM: [N x 128] @ [128 x 640]
//    BM=128 BN=64 BK=16, 8 warps (4x2), warp tile 32x32, cp.async 2-stage
//    Output routed to dstSide/srcSide compact layouts.
// ============================================================
__device__ __forceinline__ void cpa16(void* sdst, const void* gsrc, int nbytes) {
    unsigned sa = (unsigned)__cvta_generic_to_shared(sdst);
    asm volatile("cp.async.ca.shared.global [%0], [%1], 16, %2;\n"
                 :: "r"(sa), "l"(gsrc), "r"(nbytes) : "memory");
}
__device__ __forceinline__ unsigned f2tf32(float f) {
    unsigned u;
    asm("cvt.rna.tf32.f32 %0, %1;" : "=r"(u) : "f"(f));
    return u;
}

__global__ __launch_bounds__(256) void gemm_tc(const float* __restrict__ X) {
    __shared__ float As[2][128][20];   // [m][k], pad 20 -> conflict-free frag loads
    __shared__ float Bs[2][16][72];    // [k][n], pad 72

    const int tid = threadIdx.x;
    const int wid = tid >> 5, lane = tid & 31;
    const int g = lane >> 2, tc = lane & 3;
    const int wm = wid & 3, wn = wid >> 2;     // 4 x 2 warp grid
    const int bm = blockIdx.x * 128;
    const int y  = blockIdx.y;
    const int bn = y * 64;

    // load mappings
    const int arow = tid >> 1, ac0 = (tid & 1) * 8;
    const int aok = (bm + arow) < NN ? 16 : 0;
    const float* gx = X + (size_t)(bm + arow) * FIN;
    const int brow = tid >> 4, bc = (tid & 15) * 4;

    float acc[2][4][4];
    #pragma unroll
    for (int mi = 0; mi < 2; mi++)
        #pragma unroll
        for (int ni = 0; ni < 4; ni++)
            #pragma unroll
            for (int q = 0; q < 4; q++) acc[mi][ni][q] = 0.f;

    // prologue
    {
        cpa16(&As[0][arow][ac0], gx + ac0, aok);
        cpa16(&As[0][arow][ac0 + 4], gx + ac0 + 4, aok);
        cpa16(&Bs[0][brow][bc], g_Wc + (size_t)brow * NCOLS + bn + bc, 16);
        asm volatile("cp.async.commit_group;\n" ::: "memory");
    }

    #pragma unroll
    for (int t = 0; t < 8; t++) {
        const int cur = t & 1;
        if (t < 7) {
            const int nxt = cur ^ 1;
            const int k0g = (t + 1) * 16;
            cpa16(&As[nxt][arow][ac0], gx + k0g + ac0, aok);
            cpa16(&As[nxt][arow][ac0 + 4], gx + k0g + ac0 + 4, aok);
            cpa16(&Bs[nxt][brow][bc], g_Wc + (size_t)(k0g + brow) * NCOLS + bn + bc, 16);
            asm volatile("cp.async.commit_group;\n" ::: "memory");
            asm volatile("cp.async.wait_group 1;\n" ::: "memory");
        } else {
            asm volatile("cp.async.wait_group 0;\n" ::: "memory");
        }
        __syncthreads();

        #pragma unroll
        for (int ks = 0; ks < 2; ks++) {
            const int k0 = ks * 8;
            unsigned Af[2][4];
            #pragma unroll
            for (int mi = 0; mi < 2; mi++) {
                const int m0 = wm * 32 + mi * 16;
                Af[mi][0] = f2tf32(As[cur][m0 + g][k0 + tc]);
                Af[mi][1] = f2tf32(As[cur][m0 + g + 8][k0 + tc]);
                Af[mi][2] = f2tf32(As[cur][m0 + g][k0 + tc + 4]);
                Af[mi][3] = f2tf32(As[cur][m0 + g + 8][k0 + tc + 4]);
            }
            #pragma unroll
            for (int ni = 0; ni < 4; ni++) {
                const int n0 = wn * 32 + ni * 8;
                unsigned B0 = f2tf32(Bs[cur][k0 + tc][n0 + g]);
                unsigned B1 = f2tf32(Bs[cur][k0 + tc + 4][n0 + g]);
                #pragma unroll
                for (int mi = 0; mi < 2; mi++) {
                    asm volatile(
                        "mma.sync.aligned.m16n8k8.row.col.f32.tf32.tf32.f32 "
                        "{%0,%1,%2,%3}, {%4,%5,%6,%7}, {%8,%9}, {%0,%1,%2,%3};"
                        : "+f"(acc[mi][ni][0]), "+f"(acc[mi][ni][1]),
                          "+f"(acc[mi][ni][2]), "+f"(acc[mi][ni][3])
                        : "r"(Af[mi][0]), "r"(Af[mi][1]), "r"(Af[mi][2]), "r"(Af[mi][3]),
                          "r"(B0), "r"(B1));
                }
            }
        }
        __syncthreads();
    }

    // epilogue: route to compact side arrays
    float* base; int cb;
    if (y < 4)       { base = g_dstSide; cb = y * 64; }        // u_i
    else if (y < 8)  { base = g_srcSide; cb = (y - 4) * 64; }  // v_i
    else if (y == 8) { base = g_srcSide; cb = 256; }           // m_nb
    else             { base = g_dstSide; cb = 256; }           // m_self

    #pragma unroll
    for (int mi = 0; mi < 2; mi++) {
        #pragma unroll
        for (int ni = 0; ni < 4; ni++) {
            const int col = wn * 32 + ni * 8 + 2 * tc;
            const float bx = g_biasC[bn + col];
            const float by = g_biasC[bn + col + 1];
            const int r0 = bm + wm * 32 + mi * 16 + g;
            if (r0 < NN) {
                float2 o = make_float2(acc[mi][ni][0] + bx, acc[mi][ni][1] + by);
                *(float2*)(base + (size_t)r0 * SIDE + cb + col) = o;
            }
            const int r1 = r0 + 8;
            if (r1 < NN) {
                float2 o = make_float2(acc[mi][ni][2] + bx, acc[mi][ni][3] + by);
                *(float2*)(base + (size_t)r1 * SIDE + cb + col) = o;
            }
        }
    }
}

// ============================================================
// 3) CSR-by-dst build
// ============================================================
__global__ void zero_kernel() {
    int i = blockIdx.x * blockDim.x + threadIdx.x;
    if (i < NN) g_cnt[i] = 0;
}

__global__ void hist_kernel(const int* __restrict__ dst) {
    int i = blockIdx.x * blockDim.x + threadIdx.x;
    if (i < NE) atomicAdd(&g_cnt[dst[i]], 1);
}

__global__ void scan1_kernel() {
    __shared__ int sm[1024];
    const int t = threadIdx.x;
    const int i = blockIdx.x * 1024 + t;
    int v = (i < NN) ? g_cnt[i] : 0;
    sm[t] = v;
    __syncthreads();
    #pragma unroll
    for (int ofs = 1; ofs < 1024; ofs <<= 1) {
        int add = (t >= ofs) ? sm[t - ofs] : 0;
        __syncthreads();
        sm[t] += add;
        __syncthreads();
    }
    if (i < NN) g_off[i] = sm[t] - v;     // block-local exclusive
    if (t == 1023) g_blkSum[blockIdx.x] = sm[t];
}

__global__ void scan2_kernel(int nblk) {
    __shared__ int sm[64];
    const int t = threadIdx.x;
    int v = (t < nblk) ? g_blkSum[t] : 0;
    sm[t] = v;
    __syncthreads();
    #pragma unroll
    for (int ofs = 1; ofs < 64; ofs <<= 1) {
        int add = (t >= ofs) ? sm[t - ofs] : 0;
        __syncthreads();
        sm[t] += add;
        __syncthreads();
    }
    if (t < nblk) g_blkOff[t] = sm[t] - v;
    if (t == nblk - 1) g_off[NN] = sm[t];
}

__global__ void scan3_kernel() {
    const int i = blockIdx.x * 1024 + threadIdx.x;
    if (i < NN) {
        int o = g_off[i] + g_blkOff[blockIdx.x];
        g_off[i] = o;
        g_cursor[i] = o;
    }
}

__global__ void scatter_kernel(const int* __restrict__ src, const int* __restrict__ dst) {
    int i = blockIdx.x * blockDim.x + threadIdx.x;
    if (i < NE) {
        int d = dst[i];
        int pos = atomicAdd(&g_cursor[d], 1);
        g_srcSorted[pos] = src[i];
    }
}

// ============================================================
// 4) Edge aggregation (self term fused); no atomics
// ============================================================
__global__ __launch_bounds__(64) void edge_kernel(float* __restrict__ out) {
    const int n = blockIdx.x;
    const int c = threadIdx.x;
    const float* ud = g_dstSide + (size_t)n * SIDE;
    const float u0 = ud[c], u1 = ud[64 + c], u2 = ud[128 + c], u3 = ud[192 + c];
    const float mself = ud[256 + c];

    // self term
    float den, num;
    {
        const float* vs = g_srcSide + (size_t)n * SIDE;
        float s = fmaxf(u0 + vs[c], 0.f) + fmaxf(u1 + vs[64 + c], 0.f)
                + fmaxf(u2 + vs[128 + c], 0.f) + fmaxf(u3 + vs[192 + c], 0.f);
        float e = __expf(0.25f * s);
        den = e;
        num = e * mself;
    }

    const int b0 = g_off[n], b1 = g_off[n + 1];
    __shared__ int sS[128];
    for (int base = b0; base < b1; base += 128) {
        int cnt = min(128, b1 - base);
        if (base + c < b1)      sS[c]      = g_srcSorted[base + c];
        if (base + 64 + c < b1) sS[64 + c] = g_srcSorted[base + 64 + c];
        __syncthreads();
        #pragma unroll 2
        for (int j = 0; j < cnt; j++) {
            const float* p = g_srcSide + (size_t)sS[j] * SIDE;
            float v0 = p[c], v1 = p[64 + c], v2 = p[128 + c], v3 = p[192 + c];
            float m  = p[256 + c];
            float s = fmaxf(u0 + v0, 0.f) + fmaxf(u1 + v1, 0.f)
                    + fmaxf(u2 + v2, 0.f) + fmaxf(u3 + v3, 0.f);
            float w = __expf(0.25f * s);
            den += w;
            num = fmaf(w, m, num);
        }
        __syncthreads();
    }
    out[(size_t)n * 64 + c] = fmaxf(__fdividef(num, den), 0.f);
}

// ============================================================
extern "C" void kernel_launch(void* const* d_in, const int* in_sizes, int n_in,
                              void* d_out, int out_size) {
    const float* x   = (const float*)d_in[0];
    const int*   src = (const int*)d_in[1];
    const int*   dst = (const int*)d_in[2];
    const float* Wv = (const float*)d_in[3];
    const float* bv = (const float*)d_in[4];
    const float* Wn = (const float*)d_in[5];
    const float* bn = (const float*)d_in[6];
    const float* Wt = (const float*)d_in[7];
    const float* bt = (const float*)d_in[8];
    const float* Wa = (const float*)d_in[9];
    const float* ba = (const float*)d_in[10];
    float* out = (float*)d_out;

    prep_kernel<<<NCOLS, 128>>>(Wt, bt, Wa, ba, Wn, bn, Wv, bv);

    dim3 ggrid((NN + 127) / 128, 10);
    gemm_tc<<<ggrid, 256>>>(x);

    const int NB = (NN + 1023) / 1024;   // 49
    zero_kernel<<<(NN + 255) / 256, 256>>>();
    hist_kernel<<<(NE + 255) / 256, 256>>>(dst);
    scan1_kernel<<<NB, 1024>>>();
    scan2_kernel<<<1, 64>>>(NB);
    scan3_kernel<<<NB, 1024>>>();
    scatter_kernel<<<(NE + 255) / 256, 256>>>(src, dst);

    edge_kernel<<<NN, 64>>>(out);
}

// round 6
// speedup vs baseline: 2.0674x; 1.3033x over previous
#include <cuda_runtime.h>
#include <cuda_fp16.h>
#include <cstdint>

#define NN 50000
#define NE 1600000
#define FIN 128
#define FOUT 64
#define NCOLS 640
#define SIDE 320   // per-side row: 4*64 (logits) + 64 (message)

// ---- scratch ----
__device__ float  g_dstSide[(size_t)NN * SIDE];   // u0..u3 | m_self  (fp32)
__device__ __half g_srcSideH[(size_t)NN * SIDE];  // v0..v3 | m_nb    (fp16)
__device__ float  g_Wc[FIN * NCOLS];              // tf32-rounded
__device__ float  g_biasC[NCOLS];
__device__ int    g_cnt[NN];
__device__ int    g_off[NN + 1];
__device__ int    g_cursor[NN];
__device__ int    g_srcSorted[NE];
__device__ int    g_blkSum[64];
__device__ int    g_blkOff[64];

__device__ __forceinline__ unsigned f2tf32(float f) {
    unsigned u;
    asm("cvt.rna.tf32.f32 %0, %1;" : "=r"(u) : "f"(f));
    return u;
}

// ============================================================
// 1) Fold weights into Wc[128][640] (tf32-rounded) + biasC[640]
// cols [0,256): U_i   [256,512): V_i   [512,576): Wn   [576,640): Wv
// ============================================================
__global__ void prep_kernel(const float* __restrict__ Wt, const float* __restrict__ bt,
                            const float* __restrict__ Wa, const float* __restrict__ ba,
                            const float* __restrict__ Wn, const float* __restrict__ bn,
                            const float* __restrict__ Wv, const float* __restrict__ bv) {
    int col = blockIdx.x;
    int r   = threadIdx.x;
    float w;
    if (col < 512) {
        int uv = col >> 8;
        int i  = (col >> 6) & 3;
        int cc = col & 63;
        const float* wt = Wt + ((size_t)(i * FIN) + r) * FOUT;
        const float* wa = Wa + ((size_t)i * 2 * FOUT + uv * FOUT) * FOUT + cc;
        float s = 0.f;
        #pragma unroll 8
        for (int k = 0; k < FOUT; k++) s = fmaf(wt[k], wa[(size_t)k * FOUT], s);
        w = s;
        if (r == 0) {
            const float* bti = bt + i * FOUT;
            float sb = 0.f;
            for (int k = 0; k < FOUT; k++) sb = fmaf(bti[k], wa[(size_t)k * FOUT], sb);
            if (uv == 0) sb += ba[i * FOUT + cc];
            g_biasC[col] = sb;
        }
    } else if (col < 576) {
        int cc = col - 512;
        w = Wn[(size_t)r * FOUT + cc];
        if (r == 0) g_biasC[col] = bn[cc];
    } else {
        int cc = col - 576;
        w = Wv[(size_t)r * FOUT + cc];
        if (r == 0) g_biasC[col] = bv[cc];
    }
    g_Wc[(size_t)r * NCOLS + col] = __uint_as_float(f2tf32(w));
}

// ============================================================
// 2) tf32 tensor-core GEMM: [N x 128] @ [128 x 640]
//    BM=128 BN=128 BK=16, 8 warps (4m x 2n), warp tile 32x64, cp.async 2-stage
//    Each warp's 64-wide n-tile maps to exactly one 64-col group -> uniform routing.
// ============================================================
__device__ __forceinline__ void cpa16(void* sdst, const void* gsrc, int nbytes) {
    unsigned sa = (unsigned)__cvta_generic_to_shared(sdst);
    asm volatile("cp.async.ca.shared.global [%0], [%1], 16, %2;\n"
                 :: "r"(sa), "l"(gsrc), "r"(nbytes) : "memory");
}

__global__ __launch_bounds__(256) void gemm_tc(const float* __restrict__ X) {
    __shared__ float As[2][128][20];
    __shared__ float Bs[2][16][136];

    const int tid = threadIdx.x;
    const int wid = tid >> 5, lane = tid & 31;
    const int g = lane >> 2, tc = lane & 3;
    const int wm = wid & 3, wn = wid >> 2;     // 4 x 2 warp grid
    const int bm = blockIdx.x * 128;
    const int bn = blockIdx.y * 128;

    const int arow = tid >> 1, ac0 = (tid & 1) * 8;
    const int aok = (bm + arow) < NN ? 16 : 0;
    const float* gx = X + (size_t)(bm + arow) * FIN;
    const int brow = tid >> 4, bc = (tid & 15) * 8;

    float acc[2][8][4];
    #pragma unroll
    for (int mi = 0; mi < 2; mi++)
        #pragma unroll
        for (int ni = 0; ni < 8; ni++)
            #pragma unroll
            for (int q = 0; q < 4; q++) acc[mi][ni][q] = 0.f;

    {
        cpa16(&As[0][arow][ac0], gx + ac0, aok);
        cpa16(&As[0][arow][ac0 + 4], gx + ac0 + 4, aok);
        cpa16(&Bs[0][brow][bc], g_Wc + (size_t)brow * NCOLS + bn + bc, 16);
        cpa16(&Bs[0][brow][bc + 4], g_Wc + (size_t)brow * NCOLS + bn + bc + 4, 16);
        asm volatile("cp.async.commit_group;\n" ::: "memory");
    }

    #pragma unroll
    for (int t = 0; t < 8; t++) {
        const int cur = t & 1;
        if (t < 7) {
            const int nxt = cur ^ 1;
            const int k0g = (t + 1) * 16;
            cpa16(&As[nxt][arow][ac0], gx + k0g + ac0, aok);
            cpa16(&As[nxt][arow][ac0 + 4], gx + k0g + ac0 + 4, aok);
            cpa16(&Bs[nxt][brow][bc], g_Wc + (size_t)(k0g + brow) * NCOLS + bn + bc, 16);
            cpa16(&Bs[nxt][brow][bc + 4], g_Wc + (size_t)(k0g + brow) * NCOLS + bn + bc + 4, 16);
            asm volatile("cp.async.commit_group;\n" ::: "memory");
            asm volatile("cp.async.wait_group 1;\n" ::: "memory");
        } else {
            asm volatile("cp.async.wait_group 0;\n" ::: "memory");
        }
        __syncthreads();

        #pragma unroll
        for (int ks = 0; ks < 2; ks++) {
            const int k0 = ks * 8;
            unsigned Af[2][4];
            #pragma unroll
            for (int mi = 0; mi < 2; mi++) {
                const int m0 = wm * 32 + mi * 16;
                Af[mi][0] = f2tf32(As[cur][m0 + g][k0 + tc]);
                Af[mi][1] = f2tf32(As[cur][m0 + g + 8][k0 + tc]);
                Af[mi][2] = f2tf32(As[cur][m0 + g][k0 + tc + 4]);
                Af[mi][3] = f2tf32(As[cur][m0 + g + 8][k0 + tc + 4]);
            }
            #pragma unroll
            for (int ni = 0; ni < 8; ni++) {
                const int n0 = wn * 64 + ni * 8;
                unsigned B0 = __float_as_uint(Bs[cur][k0 + tc][n0 + g]);      // pre-rounded
                unsigned B1 = __float_as_uint(Bs[cur][k0 + tc + 4][n0 + g]);
                #pragma unroll
                for (int mi = 0; mi < 2; mi++) {
                    asm volatile(
                        "mma.sync.aligned.m16n8k8.row.col.f32.tf32.tf32.f32 "
                        "{%0,%1,%2,%3}, {%4,%5,%6,%7}, {%8,%9}, {%0,%1,%2,%3};"
                        : "+f"(acc[mi][ni][0]), "+f"(acc[mi][ni][1]),
                          "+f"(acc[mi][ni][2]), "+f"(acc[mi][ni][3])
                        : "r"(Af[mi][0]), "r"(Af[mi][1]), "r"(Af[mi][2]), "r"(Af[mi][3]),
                          "r"(B0), "r"(B1));
                }
            }
        }
        __syncthreads();
    }

    // routing: this warp's 64-col group
    const int g64 = (bn >> 6) + wn;           // 0..9
    float*  dbase = nullptr; __half* sbase = nullptr; int cb;
    if (g64 < 4)       { dbase = g_dstSide;  cb = g64 * 64; }
    else if (g64 < 8)  { sbase = g_srcSideH; cb = (g64 - 4) * 64; }
    else if (g64 == 8) { sbase = g_srcSideH; cb = 256; }
    else               { dbase = g_dstSide;  cb = 256; }

    #pragma unroll
    for (int mi = 0; mi < 2; mi++) {
        #pragma unroll
        for (int ni = 0; ni < 8; ni++) {
            const int loc = ni * 8 + 2 * tc;                 // 0..62 within group
            const float bx = g_biasC[g64 * 64 + loc];
            const float by = g_biasC[g64 * 64 + loc + 1];
            const int r0 = bm + wm * 32 + mi * 16 + g;
            const int r1 = r0 + 8;
            float2 o0 = make_float2(acc[mi][ni][0] + bx, acc[mi][ni][1] + by);
            float2 o1 = make_float2(acc[mi][ni][2] + bx, acc[mi][ni][3] + by);
            if (dbase) {
                if (r0 < NN) *(float2*)(dbase + (size_t)r0 * SIDE + cb + loc) = o0;
                if (r1 < NN) *(float2*)(dbase + (size_t)r1 * SIDE + cb + loc) = o1;
            } else {
                if (r0 < NN) *(__half2*)(sbase + (size_t)r0 * SIDE + cb + loc) = __float22half2_rn(o0);
                if (r1 < NN) *(__half2*)(sbase + (size_t)r1 * SIDE + cb + loc) = __float22half2_rn(o1);
            }
        }
    }
}

// ============================================================
// 3) CSR-by-dst build (vectorized)
// ============================================================
__global__ void zero_kernel() {
    int i = blockIdx.x * blockDim.x + threadIdx.x;
    if (i < NN) g_cnt[i] = 0;
}

__global__ void hist_kernel(const int* __restrict__ dst) {
    int i = blockIdx.x * blockDim.x + threadIdx.x;
    if (i < NE / 4) {
        int4 d = ((const int4*)dst)[i];
        atomicAdd(&g_cnt[d.x], 1);
        atomicAdd(&g_cnt[d.y], 1);
        atomicAdd(&g_cnt[d.z], 1);
        atomicAdd(&g_cnt[d.w], 1);
    }
}

__global__ void scan1_kernel() {
    __shared__ int sm[1024];
    const int t = threadIdx.x;
    const int i = blockIdx.x * 1024 + t;
    int v = (i < NN) ? g_cnt[i] : 0;
    sm[t] = v;
    __syncthreads();
    #pragma unroll
    for (int ofs = 1; ofs < 1024; ofs <<= 1) {
        int add = (t >= ofs) ? sm[t - ofs] : 0;
        __syncthreads();
        sm[t] += add;
        __syncthreads();
    }
    if (i < NN) g_off[i] = sm[t] - v;
    if (t == 1023) g_blkSum[blockIdx.x] = sm[t];
}

__global__ void scan2_kernel(int nblk) {
    __shared__ int sm[64];
    const int t = threadIdx.x;
    int v = (t < nblk) ? g_blkSum[t] : 0;
    sm[t] = v;
    __syncthreads();
    #pragma unroll
    for (int ofs = 1; ofs < 64; ofs <<= 1) {
        int add = (t >= ofs) ? sm[t - ofs] : 0;
        __syncthreads();
        sm[t] += add;
        __syncthreads();
    }
    if (t < nblk) g_blkOff[t] = sm[t] - v;
    if (t == nblk - 1) g_off[NN] = sm[t];
}

__global__ void scan3_kernel() {
    const int i = blockIdx.x * 1024 + threadIdx.x;
    if (i < NN) {
        int o = g_off[i] + g_blkOff[blockIdx.x];
        g_off[i] = o;
        g_cursor[i] = o;
    }
}

__global__ void scatter_kernel(const int* __restrict__ src, const int* __restrict__ dst) {
    int i = blockIdx.x * blockDim.x + threadIdx.x;
    if (i < NE / 4) {
        int4 s = ((const int4*)src)[i];
        int4 d = ((const int4*)dst)[i];
        g_srcSorted[atomicAdd(&g_cursor[d.x], 1)] = s.x;
        g_srcSorted[atomicAdd(&g_cursor[d.y], 1)] = s.y;
        g_srcSorted[atomicAdd(&g_cursor[d.z], 1)] = s.z;
        g_srcSorted[atomicAdd(&g_cursor[d.w], 1)] = s.w;
    }
}

// ============================================================
// 4) Edge aggregation: one WARP per dst node, half2 per thread,
//    src indices via shfl; self term fused; no atomics, no smem.
// ============================================================
__global__ __launch_bounds__(256) void edge_kernel(float* __restrict__ out) {
    const int warp = threadIdx.x >> 5, lane = threadIdx.x & 31;
    const int n = blockIdx.x * 8 + warp;
    if (n >= NN) return;

    const float2* ud = (const float2*)(g_dstSide + (size_t)n * SIDE);
    __half2 uh[4];
    #pragma unroll
    for (int i = 0; i < 4; i++) uh[i] = __float22half2_rn(ud[i * 32 + lane]);
    const float2 msf = ud[128 + lane];
    const __half2 zero2 = __float2half2_rn(0.f);

    float2 den, num;
    {
        const __half2* vs = (const __half2*)(g_srcSideH + (size_t)n * SIDE);
        __half2 s2 = __hmax2(__hadd2(uh[0], vs[lane]), zero2);
        s2 = __hadd2(s2, __hmax2(__hadd2(uh[1], vs[32 + lane]), zero2));
        s2 = __hadd2(s2, __hmax2(__hadd2(uh[2], vs[64 + lane]), zero2));
        s2 = __hadd2(s2, __hmax2(__hadd2(uh[3], vs[96 + lane]), zero2));
        float2 s = __half22float2(s2);
        float e0 = __expf(0.25f * s.x), e1 = __expf(0.25f * s.y);
        den = make_float2(e0, e1);
        num = make_float2(e0 * msf.x, e1 * msf.y);
    }

    const int b0 = g_off[n], b1 = g_off[n + 1];
    for (int base = b0; base < b1; base += 32) {
        int myIdx = (base + lane < b1) ? g_srcSorted[base + lane] : 0;
        const int cnt = min(32, b1 - base);
        #pragma unroll 4
        for (int j = 0; j < cnt; j++) {
            const int sidx = __shfl_sync(0xffffffff, myIdx, j);
            const __half2* p = (const __half2*)(g_srcSideH + (size_t)sidx * SIDE);
            __half2 s2 = __hmax2(__hadd2(uh[0], p[lane]), zero2);
            s2 = __hadd2(s2, __hmax2(__hadd2(uh[1], p[32 + lane]), zero2));
            s2 = __hadd2(s2, __hmax2(__hadd2(uh[2], p[64 + lane]), zero2));
            s2 = __hadd2(s2, __hmax2(__hadd2(uh[3], p[96 + lane]), zero2));
            float2 mm = __half22float2(p[128 + lane]);
            float2 s = __half22float2(s2);
            float w0 = __expf(0.25f * s.x), w1 = __expf(0.25f * s.y);
            den.x += w0;                den.y += w1;
            num.x = fmaf(w0, mm.x, num.x); num.y = fmaf(w1, mm.y, num.y);
        }
    }
    float2 o;
    o.x = fmaxf(__fdividef(num.x, den.x), 0.f);
    o.y = fmaxf(__fdividef(num.y, den.y), 0.f);
    ((float2*)out)[(size_t)n * 32 + lane] = o;
}

// ============================================================
extern "C" void kernel_launch(void* const* d_in, const int* in_sizes, int n_in,
                              void* d_out, int out_size) {
    const float* x   = (const float*)d_in[0];
    const int*   src = (const int*)d_in[1];
    const int*   dst = (const int*)d_in[2];
    const float* Wv = (const float*)d_in[3];
    const float* bv = (const float*)d_in[4];
    const float* Wn = (const float*)d_in[5];
    const float* bn = (const float*)d_in[6];
    const float* Wt = (const float*)d_in[7];
    const float* bt = (const float*)d_in[8];
    const float* Wa = (const float*)d_in[9];
    const float* ba = (const float*)d_in[10];
    float* out = (float*)d_out;

    prep_kernel<<<NCOLS, 128>>>(Wt, bt, Wa, ba, Wn, bn, Wv, bv);

    dim3 ggrid((NN + 127) / 128, 5);
    gemm_tc<<<ggrid, 256>>>(x);

    const int NB = (NN + 1023) / 1024;   // 49
    zero_kernel<<<(NN + 255) / 256, 256>>>();
    hist_kernel<<<(NE / 4 + 255) / 256, 256>>>(dst);
    scan1_kernel<<<NB, 1024>>>();
    scan2_kernel<<<1, 64>>>(NB);
    scan3_kernel<<<NB, 1024>>>();
    scatter_kernel<<<(NE / 4 + 255) / 256, 256>>>(src, dst);

    edge_kernel<<<(NN + 7) / 8, 256>>>(out);
}